// round 2
// baseline (speedup 1.0000x reference)
#include <cuda_runtime.h>
#include <cstdint>

// Problem constants (fixed shapes for this problem)
#define Bc 8
#define Hc 1024
#define Ec 512
#define Vc 32000
#define Tc 100
#define KVc 1536   // H + E   (x_v width)
#define KKc 2560   // 2H + E  (x_k width)

#define GRID_MAIN 250          // 8 warps/block * 4 tiles/warp * 250 = 8000 tiles exactly
#define WARPS_TOTAL (GRID_MAIN * 8)
#define NTILES (Vc / 4)        // 8000 warp-tiles of 4 vocab rows

// Scratch (device globals; no runtime allocation allowed)
__device__ int   g_cnt[Bc * Vc];               // topic word counts per batch
__device__ float g_ekval[Bc * Vc];             // e_k values (valid only where cnt>0)
__device__ float g_psum[GRID_MAIN * Bc];       // per-BLOCK partial softmax sums
__device__ float g_rinv[Bc];                   // reciprocal row sums

// ---------------------------------------------------------------------------
// Kernel 1: zero the count array (1 MB)
// ---------------------------------------------------------------------------
__global__ void zero_cnt_kernel() {
    int i = blockIdx.x * blockDim.x + threadIdx.x;   // 64000 int4
    ((int4*)g_cnt)[i] = make_int4(0, 0, 0, 0);
}

// ---------------------------------------------------------------------------
// Kernel 2: count topic words + compute e_k for each (b, topic word) pair.
// One warp per (b,t) pair. 800 pairs total. Duplicates write identical e_k
// values (benign); counts accumulate via integer atomics (exact).
// ---------------------------------------------------------------------------
__global__ void count_ek_kernel(const int*   __restrict__ topics,
                                const float* __restrict__ outp,
                                const float* __restrict__ inp,
                                const float* __restrict__ ctx,
                                const float* __restrict__ WK,
                                const float* __restrict__ bK) {
    int pair = blockIdx.x * 8 + (threadIdx.x >> 5);
    int lane = threadIdx.x & 31;
    if (pair >= Bc * Tc) return;
    int b = pair / Tc;
    int idx = topics[pair];
    if (idx == 0) return;                       // pad word contributes nothing
    if (lane == 0) atomicAdd(&g_cnt[b * Vc + idx], 1);

    const float* wrow = WK + (size_t)idx * KKc;
    float s = 0.f;
    #pragma unroll
    for (int c = 0; c < KKc; c += 128) {
        int cc = c + lane * 4;
        float4 wv = *(const float4*)(wrow + cc);
        float4 xv;
        if (cc < Hc)            xv = *(const float4*)(outp + b * Hc + cc);
        else if (cc < Hc + Ec)  xv = *(const float4*)(inp  + b * Ec + (cc - Hc));
        else                    xv = *(const float4*)(ctx  + b * Hc + (cc - Hc - Ec));
        s += wv.x * xv.x + wv.y * xv.y + wv.z * xv.z + wv.w * xv.w;
    }
    #pragma unroll
    for (int h = 16; h >= 1; h >>= 1) s += __shfl_xor_sync(0xffffffffu, s, h);
    if (lane == 0) g_ekval[b * Vc + idx] = s + bK[idx];
}

// ---------------------------------------------------------------------------
// Kernel 3: main GEMV + gate + tanh + exp + block-level partial sums.
// Each warp processes exactly 4 tiles of (4 vocab rows x 8 batches).
//   - x_v held in shared memory [8][1536] (48 KB, conflict-free float4 LDS)
//   - lanes span columns: coalesced float4 LDG of W_V
//   - 31-shuffle butterfly transpose-reduce: lane l ends with the full dot
//     for (row = l>>3, batch = l&7)
//   - per-block smem reduction of softmax partial sums (deterministic)
// ---------------------------------------------------------------------------
__global__ void __launch_bounds__(256) main_kernel(const float* __restrict__ outp,
                                                   const float* __restrict__ inp,
                                                   const float* __restrict__ WV,
                                                   const float* __restrict__ bV,
                                                   float* __restrict__ out) {
    __shared__ float xs[Bc * KVc];   // 49152 bytes (exactly 48 KB)
    __shared__ float sm_ps[8 * Bc];  // per-warp batch sums

    // cooperative fill of x_v = concat(output, input_step) per batch
    for (int i = threadIdx.x; i < (Bc * KVc) / 4; i += blockDim.x) {
        int fi = i * 4;
        int b = fi / KVc;
        int c = fi % KVc;
        float4 v;
        if (c < Hc) v = *(const float4*)(outp + b * Hc + c);
        else        v = *(const float4*)(inp  + b * Ec + (c - Hc));
        *(float4*)(xs + fi) = v;
    }
    __syncthreads();

    int warp = threadIdx.x >> 5;
    int lane = threadIdx.x & 31;
    int b = lane & 7;
    int r = lane >> 3;
    float lsum = 0.f;

    int wid = blockIdx.x * 8 + warp;
    #pragma unroll 1
    for (int tile = wid; tile < NTILES; tile += WARPS_TOTAL) {
        int w0 = tile * 4;
        float acc[32];
        #pragma unroll
        for (int j = 0; j < 32; j++) acc[j] = 0.f;

        const float* Wp = WV + (size_t)w0 * KVc + lane * 4;

        #pragma unroll 2
        for (int it = 0; it < 12; it++) {
            int cb = it * 128;
            float4 w0v = *(const float4*)(Wp + cb);
            float4 w1v = *(const float4*)(Wp + KVc + cb);
            float4 w2v = *(const float4*)(Wp + 2 * KVc + cb);
            float4 w3v = *(const float4*)(Wp + 3 * KVc + cb);
            int xb = cb + lane * 4;
            #pragma unroll
            for (int bb = 0; bb < 8; bb++) {
                float4 xv = *(const float4*)(xs + bb * KVc + xb);
                acc[0 * 8 + bb] = fmaf(w0v.x, xv.x, acc[0 * 8 + bb]);
                acc[0 * 8 + bb] = fmaf(w0v.y, xv.y, acc[0 * 8 + bb]);
                acc[0 * 8 + bb] = fmaf(w0v.z, xv.z, acc[0 * 8 + bb]);
                acc[0 * 8 + bb] = fmaf(w0v.w, xv.w, acc[0 * 8 + bb]);
                acc[1 * 8 + bb] = fmaf(w1v.x, xv.x, acc[1 * 8 + bb]);
                acc[1 * 8 + bb] = fmaf(w1v.y, xv.y, acc[1 * 8 + bb]);
                acc[1 * 8 + bb] = fmaf(w1v.z, xv.z, acc[1 * 8 + bb]);
                acc[1 * 8 + bb] = fmaf(w1v.w, xv.w, acc[1 * 8 + bb]);
                acc[2 * 8 + bb] = fmaf(w2v.x, xv.x, acc[2 * 8 + bb]);
                acc[2 * 8 + bb] = fmaf(w2v.y, xv.y, acc[2 * 8 + bb]);
                acc[2 * 8 + bb] = fmaf(w2v.z, xv.z, acc[2 * 8 + bb]);
                acc[2 * 8 + bb] = fmaf(w2v.w, xv.w, acc[2 * 8 + bb]);
                acc[3 * 8 + bb] = fmaf(w3v.x, xv.x, acc[3 * 8 + bb]);
                acc[3 * 8 + bb] = fmaf(w3v.y, xv.y, acc[3 * 8 + bb]);
                acc[3 * 8 + bb] = fmaf(w3v.z, xv.z, acc[3 * 8 + bb]);
                acc[3 * 8 + bb] = fmaf(w3v.w, xv.w, acc[3 * 8 + bb]);
            }
        }

        // butterfly transpose-reduce: 31 shuffles; lane l ends with sum of acc[l]
        #pragma unroll
        for (int h = 16; h >= 1; h >>= 1) {
            #pragma unroll
            for (int j = 0; j < h; j++) {
                float lo = acc[j];
                float hi = acc[j + h];
                float mine = (lane & h) ? hi : lo;
                float send = (lane & h) ? lo : hi;
                float recv = __shfl_xor_sync(0xffffffffu, send, h);
                acc[j] = mine + recv;
            }
        }

        int w = w0 + r;
        float ev = acc[0] + __ldg(bV + w);
        int cnt = g_cnt[b * Vc + w];
        float en = (cnt == 0) ? ev : (float)cnt * g_ekval[b * Vc + w];
        en = tanhf(en);
        float p = __expf(en);
        out[b * Vc + w] = p;
        lsum += p;
    }

    // lanes {l, l^8, l^16, l^24} share batch b = l&7 -> combine, lane<8 writes
    lsum += __shfl_xor_sync(0xffffffffu, lsum, 8);
    lsum += __shfl_xor_sync(0xffffffffu, lsum, 16);
    if (lane < 8) sm_ps[warp * 8 + b] = lsum;
    __syncthreads();

    // block-level deterministic combine: 8 warps -> one value per batch
    if (threadIdx.x < 8) {
        float s = 0.f;
        #pragma unroll
        for (int wv = 0; wv < 8; wv++) s += sm_ps[wv * 8 + threadIdx.x];
        g_psum[blockIdx.x * 8 + threadIdx.x] = s;
    }
}

// ---------------------------------------------------------------------------
// Kernel 4: deterministic reduction of partial sums -> reciprocal per batch
// 8 warps (one per batch), ~8 loads per lane.
// ---------------------------------------------------------------------------
__global__ void reduce_kernel() {
    int warp = threadIdx.x >> 5;   // warp == batch
    int lane = threadIdx.x & 31;
    float s = 0.f;
    for (int i = lane; i < GRID_MAIN; i += 32)
        s += g_psum[i * 8 + warp];
    #pragma unroll
    for (int h = 16; h >= 1; h >>= 1) s += __shfl_xor_sync(0xffffffffu, s, h);
    if (lane == 0) g_rinv[warp] = 1.0f / s;
}

// ---------------------------------------------------------------------------
// Kernel 5: normalize
// ---------------------------------------------------------------------------
__global__ void norm_kernel(float* __restrict__ out) {
    int b = blockIdx.y;
    int i = blockIdx.x * blockDim.x + threadIdx.x;   // 125*256 == 32000 exactly
    out[b * Vc + i] *= g_rinv[b];
}

// ---------------------------------------------------------------------------
// Launch
// Input order: output, input_step, context, topic_indexs, [topic_length],
//              W_V, b_V, W_K, b_K   (topic_length scalar may or may not be a tensor)
// ---------------------------------------------------------------------------
extern "C" void kernel_launch(void* const* d_in, const int* in_sizes, int n_in,
                              void* d_out, int out_size) {
    const float* outp   = (const float*)d_in[0];
    const float* inp    = (const float*)d_in[1];
    const float* ctx    = (const float*)d_in[2];
    const int*   topics = (const int*)d_in[3];

    int base = 4;
    if (n_in >= 9 && in_sizes[4] <= 4) base = 5;   // skip topic_length scalar

    const float* WV = (const float*)d_in[base + 0];
    const float* bV = (const float*)d_in[base + 1];
    const float* WK = (const float*)d_in[base + 2];
    const float* bK = (const float*)d_in[base + 3];
    float* out = (float*)d_out;

    zero_cnt_kernel<<<(Bc * Vc / 4 + 255) / 256, 256>>>();
    count_ek_kernel<<<(Bc * Tc + 7) / 8, 256>>>(topics, outp, inp, ctx, WK, bK);
    main_kernel<<<GRID_MAIN, 256>>>(outp, inp, WV, bV, out);
    reduce_kernel<<<1, 256>>>();
    norm_kernel<<<dim3(Vc / 256, Bc), 256>>>(out);
}

// round 3
// speedup vs baseline: 1.2012x; 1.2012x over previous
#include <cuda_runtime.h>
#include <cstdint>

// Problem constants (fixed shapes for this problem)
#define Bc 8
#define Hc 1024
#define Ec 512
#define Vc 32000
#define Tc 100
#define KVc 1536   // H + E   (x_v width)
#define KKc 2560   // 2H + E  (x_k width)

#define GRID_MAIN 296          // 2 blocks per SM on 148 SMs, single wave
#define NTILES (Vc / 4)        // 8000 warp-tiles of 4 vocab rows
// 8000 = 296*27 + 8  -> first 8 blocks take 28 tiles, rest take 27

// Scratch (device globals; zero-initialized at module load, no runtime alloc)
__device__ int   g_cnt[Bc * Vc];               // topic word counts (kept zero between runs)
__device__ float g_ekval[Bc * Vc];             // e_k values (valid only where cnt>0)
__device__ float g_psum[GRID_MAIN * Bc];       // per-BLOCK partial softmax sums
__device__ float g_rinv[Bc];                   // (unused placeholder)

// ---------------------------------------------------------------------------
// Kernel 1: count topic words + compute e_k for each (b, topic word) pair.
// One warp per (b,t) pair. 800 pairs total. Duplicates write identical e_k
// values (benign); counts accumulate via integer atomics (exact).
// g_cnt is guaranteed all-zero on entry (zero-init + cleanup in norm kernel).
// ---------------------------------------------------------------------------
__global__ void count_ek_kernel(const int*   __restrict__ topics,
                                const float* __restrict__ outp,
                                const float* __restrict__ inp,
                                const float* __restrict__ ctx,
                                const float* __restrict__ WK,
                                const float* __restrict__ bK) {
    int pair = blockIdx.x * 8 + (threadIdx.x >> 5);
    int lane = threadIdx.x & 31;
    if (pair >= Bc * Tc) return;
    int b = pair / Tc;
    int idx = topics[pair];
    if (idx == 0) return;                       // pad word contributes nothing
    if (lane == 0) atomicAdd(&g_cnt[b * Vc + idx], 1);

    const float* wrow = WK + (size_t)idx * KKc;
    float s = 0.f;
    #pragma unroll
    for (int c = 0; c < KKc; c += 128) {
        int cc = c + lane * 4;
        float4 wv = *(const float4*)(wrow + cc);
        float4 xv;
        if (cc < Hc)            xv = *(const float4*)(outp + b * Hc + cc);
        else if (cc < Hc + Ec)  xv = *(const float4*)(inp  + b * Ec + (cc - Hc));
        else                    xv = *(const float4*)(ctx  + b * Hc + (cc - Hc - Ec));
        s += wv.x * xv.x + wv.y * xv.y + wv.z * xv.z + wv.w * xv.w;
    }
    #pragma unroll
    for (int h = 16; h >= 1; h >>= 1) s += __shfl_xor_sync(0xffffffffu, s, h);
    if (lane == 0) g_ekval[b * Vc + idx] = s + bK[idx];
}

// ---------------------------------------------------------------------------
// Kernel 2: main GEMV + gate + tanh + exp + block-level partial sums.
// grid = 296 (2 blocks/SM everywhere). Block takes a contiguous chunk of
// 27 or 28 tiles; warps stride over the chunk. Per-SM work is 54-56 tiles.
//   - x_v held in shared memory [8][1536] (48 KB)
//   - W_V loads double-buffered (prefetch next 4x float4 while FMA-ing)
//   - 31-shuffle butterfly transpose-reduce: lane l -> (row=l>>3, batch=l&7)
// ---------------------------------------------------------------------------
__global__ void __launch_bounds__(256, 2) main_kernel(const float* __restrict__ outp,
                                                      const float* __restrict__ inp,
                                                      const float* __restrict__ WV,
                                                      const float* __restrict__ bV,
                                                      float* __restrict__ out) {
    __shared__ float xs[Bc * KVc];   // 49152 bytes (exactly 48 KB)
    __shared__ float sm_ps[8 * Bc];  // per-warp batch sums

    // cooperative fill of x_v = concat(output, input_step) per batch
    for (int i = threadIdx.x; i < (Bc * KVc) / 4; i += blockDim.x) {
        int fi = i * 4;
        int b = fi / KVc;
        int c = fi % KVc;
        float4 v;
        if (c < Hc) v = *(const float4*)(outp + b * Hc + c);
        else        v = *(const float4*)(inp  + b * Ec + (c - Hc));
        *(float4*)(xs + fi) = v;
    }
    __syncthreads();

    int warp = threadIdx.x >> 5;
    int lane = threadIdx.x & 31;
    int b = lane & 7;
    int r = lane >> 3;
    float lsum = 0.f;

    int blk = blockIdx.x;
    int tbase = blk * 27 + (blk < 8 ? blk : 8);
    int tcnt  = 27 + (blk < 8 ? 1 : 0);

    #pragma unroll 1
    for (int k = warp; k < tcnt; k += 8) {
        int tile = tbase + k;
        int w0 = tile * 4;
        float acc[32];
        #pragma unroll
        for (int j = 0; j < 32; j++) acc[j] = 0.f;

        const float* Wp = WV + (size_t)w0 * KVc + lane * 4;

        // double-buffered W loads
        float4 wc0 = *(const float4*)(Wp);
        float4 wc1 = *(const float4*)(Wp + KVc);
        float4 wc2 = *(const float4*)(Wp + 2 * KVc);
        float4 wc3 = *(const float4*)(Wp + 3 * KVc);

        #pragma unroll 2
        for (int it = 0; it < 12; it++) {
            float4 wn0, wn1, wn2, wn3;
            if (it < 11) {
                const float* Pn = Wp + (it + 1) * 128;
                wn0 = *(const float4*)(Pn);
                wn1 = *(const float4*)(Pn + KVc);
                wn2 = *(const float4*)(Pn + 2 * KVc);
                wn3 = *(const float4*)(Pn + 3 * KVc);
            }
            int xb = it * 128 + lane * 4;
            #pragma unroll
            for (int bb = 0; bb < 8; bb++) {
                float4 xv = *(const float4*)(xs + bb * KVc + xb);
                acc[0 * 8 + bb] = fmaf(wc0.x, xv.x, acc[0 * 8 + bb]);
                acc[0 * 8 + bb] = fmaf(wc0.y, xv.y, acc[0 * 8 + bb]);
                acc[0 * 8 + bb] = fmaf(wc0.z, xv.z, acc[0 * 8 + bb]);
                acc[0 * 8 + bb] = fmaf(wc0.w, xv.w, acc[0 * 8 + bb]);
                acc[1 * 8 + bb] = fmaf(wc1.x, xv.x, acc[1 * 8 + bb]);
                acc[1 * 8 + bb] = fmaf(wc1.y, xv.y, acc[1 * 8 + bb]);
                acc[1 * 8 + bb] = fmaf(wc1.z, xv.z, acc[1 * 8 + bb]);
                acc[1 * 8 + bb] = fmaf(wc1.w, xv.w, acc[1 * 8 + bb]);
                acc[2 * 8 + bb] = fmaf(wc2.x, xv.x, acc[2 * 8 + bb]);
                acc[2 * 8 + bb] = fmaf(wc2.y, xv.y, acc[2 * 8 + bb]);
                acc[2 * 8 + bb] = fmaf(wc2.z, xv.z, acc[2 * 8 + bb]);
                acc[2 * 8 + bb] = fmaf(wc2.w, xv.w, acc[2 * 8 + bb]);
                acc[3 * 8 + bb] = fmaf(wc3.x, xv.x, acc[3 * 8 + bb]);
                acc[3 * 8 + bb] = fmaf(wc3.y, xv.y, acc[3 * 8 + bb]);
                acc[3 * 8 + bb] = fmaf(wc3.z, xv.z, acc[3 * 8 + bb]);
                acc[3 * 8 + bb] = fmaf(wc3.w, xv.w, acc[3 * 8 + bb]);
            }
            wc0 = wn0; wc1 = wn1; wc2 = wn2; wc3 = wn3;
        }

        // butterfly transpose-reduce: 31 shuffles; lane l ends with sum of acc[l]
        #pragma unroll
        for (int h = 16; h >= 1; h >>= 1) {
            #pragma unroll
            for (int j = 0; j < h; j++) {
                float lo = acc[j];
                float hi = acc[j + h];
                float mine = (lane & h) ? hi : lo;
                float send = (lane & h) ? lo : hi;
                float recv = __shfl_xor_sync(0xffffffffu, send, h);
                acc[j] = mine + recv;
            }
        }

        int w = w0 + r;
        float ev = acc[0] + __ldg(bV + w);
        int cnt = g_cnt[b * Vc + w];
        float en = (cnt == 0) ? ev : (float)cnt * g_ekval[b * Vc + w];
        en = tanhf(en);
        float p = __expf(en);
        out[b * Vc + w] = p;
        lsum += p;
    }

    // lanes {l, l^8, l^16, l^24} share batch b = l&7 -> combine, lane<8 writes
    lsum += __shfl_xor_sync(0xffffffffu, lsum, 8);
    lsum += __shfl_xor_sync(0xffffffffu, lsum, 16);
    if (lane < 8) sm_ps[warp * 8 + b] = lsum;
    __syncthreads();

    // block-level deterministic combine: 8 warps -> one value per batch
    if (threadIdx.x < 8) {
        float s = 0.f;
        #pragma unroll
        for (int wv = 0; wv < 8; wv++) s += sm_ps[wv * 8 + threadIdx.x];
        g_psum[blockIdx.x * 8 + threadIdx.x] = s;
    }
}

// ---------------------------------------------------------------------------
// Kernel 3: fused reduce + normalize + g_cnt cleanup.
// grid (125, 8), 256 threads. Each block redundantly (but deterministically)
// reduces the 296 per-block partials for its batch (L2-resident), then
// normalizes its 256-element slice. Blocks at x==0 re-zero the g_cnt entries
// touched by this run, restoring the all-zero invariant for the next replay.
// ---------------------------------------------------------------------------
__global__ void norm_kernel(float* __restrict__ out, const int* __restrict__ topics) {
    int b = blockIdx.y;
    int tid = threadIdx.x;
    __shared__ float ssum[8];
    __shared__ float srinv;

    float s = 0.f;
    if (tid < GRID_MAIN)       s += g_psum[tid * 8 + b];
    if (tid + 256 < GRID_MAIN) s += g_psum[(tid + 256) * 8 + b];
    #pragma unroll
    for (int h = 16; h >= 1; h >>= 1) s += __shfl_xor_sync(0xffffffffu, s, h);
    if ((tid & 31) == 0) ssum[tid >> 5] = s;
    __syncthreads();
    if (tid == 0) {
        float t = 0.f;
        #pragma unroll
        for (int w = 0; w < 8; w++) t += ssum[w];
        srinv = 1.0f / t;
    }
    __syncthreads();

    // cleanup: restore g_cnt to all-zero (indices touched this run only)
    if (blockIdx.x == 0) {
        for (int t = tid; t < Tc; t += 256)
            g_cnt[b * Vc + topics[b * Tc + t]] = 0;
    }

    int i = blockIdx.x * 256 + tid;   // 125*256 == 32000 exactly
    out[b * Vc + i] *= srinv;
}

// ---------------------------------------------------------------------------
// Launch (3 kernels)
// Input order: output, input_step, context, topic_indexs, [topic_length],
//              W_V, b_V, W_K, b_K
// ---------------------------------------------------------------------------
extern "C" void kernel_launch(void* const* d_in, const int* in_sizes, int n_in,
                              void* d_out, int out_size) {
    const float* outp   = (const float*)d_in[0];
    const float* inp    = (const float*)d_in[1];
    const float* ctx    = (const float*)d_in[2];
    const int*   topics = (const int*)d_in[3];

    int base = 4;
    if (n_in >= 9 && in_sizes[4] <= 4) base = 5;   // skip topic_length scalar

    const float* WV = (const float*)d_in[base + 0];
    const float* bV = (const float*)d_in[base + 1];
    const float* WK = (const float*)d_in[base + 2];
    const float* bK = (const float*)d_in[base + 3];
    float* out = (float*)d_out;

    count_ek_kernel<<<(Bc * Tc + 7) / 8, 256>>>(topics, outp, inp, ctx, WK, bK);
    main_kernel<<<GRID_MAIN, 256>>>(outp, inp, WV, bV, out);
    norm_kernel<<<dim3(Vc / 256, Bc), 256>>>(out, topics);
}